// round 15
// baseline (speedup 1.0000x reference)
#include <cuda_runtime.h>
#include <cuda_fp16.h>
#include <math.h>
#include <stdint.h>

#define B 64
#define L 256
#define H 1024
#define P 64
#define A 512
#define T 8
#define F (H + 2 * P)   // 1152
#define M_TOT (B * L)   // 16384
#define K_ENT (4 * H)   // 4096

// ---------------- scratch (device globals; no allocation allowed) ----------
__device__ __half g_ef_h[B * K_ENT];         // entity_features fp16 [B, 4H]
__device__ __half g_went_h[A * K_ENT];       // W_ent^T fp16 [A, 4H]
__device__ float g_dense_ent[B * A];         // [B, A]
__device__ float g_vu_part[4][B * L];        // vu partials (per n-quarter)
__device__ __half g_pf_h[M_TOT * F];         // pos_features fp16 [M, F]
__device__ __half g_wp_h[A * F];             // W_pos^T fp16 [A, F]

// ---------------- helpers --------------------------------------------------
__device__ __forceinline__ uint32_t smem_u32(const void* p) {
    uint32_t a;
    asm("{ .reg .u64 t; cvta.to.shared.u64 t, %1; cvt.u32.u64 %0, t; }" : "=r"(a) : "l"(p));
    return a;
}

#define CP_ASYNC16(smem, gmem) \
    asm volatile("cp.async.cg.shared.global [%0], [%1], 16;" :: "r"(smem), "l"(gmem))
#define CP_COMMIT() asm volatile("cp.async.commit_group;" ::: "memory")
#define CP_WAIT1()  asm volatile("cp.async.wait_group 1;" ::: "memory")
#define CP_WAIT2()  asm volatile("cp.async.wait_group 2;" ::: "memory")
#define CP_WAIT0()  asm volatile("cp.async.wait_group 0;" ::: "memory")

#define LDSM4(r0, r1, r2, r3, addr) \
    asm volatile("ldmatrix.sync.aligned.m8n8.x4.shared.b16 {%0,%1,%2,%3}, [%4];" \
        : "=r"(r0), "=r"(r1), "=r"(r2), "=r"(r3) : "r"(addr))

#define MMA16816(d, a, bb) \
    asm volatile("mma.sync.aligned.m16n8k16.row.col.f32.f16.f16.f32 " \
        "{%0,%1,%2,%3}, {%4,%5,%6,%7}, {%8,%9}, {%0,%1,%2,%3};" \
        : "+f"((d)[0]), "+f"((d)[1]), "+f"((d)[2]), "+f"((d)[3]) \
        : "r"((a)[0]), "r"((a)[1]), "r"((a)[2]), "r"((a)[3]), "r"((bb)[0]), "r"((bb)[1]))

// ---------------------------------------------------------------------------
// K_PREP: fused pf->fp16, W_pos^T->fp16, W_ent^T->fp16, entity prep + zeroing.
// grid = 16384 + 576 + 2048 + 64 = 19072 CTAs; 256 threads.
// ---------------------------------------------------------------------------
#define NB_PF  M_TOT
#define NB_WP  ((A / 32) * (F / 32))      // 576
#define NB_WE  ((A / 32) * (K_ENT / 32))  // 2048
#define NB_ENT B

__global__ void __launch_bounds__(256)
k_prep(const float* __restrict__ wh,
       const float* __restrict__ pe1,
       const float* __restrict__ pe2,
       const float* __restrict__ Wp,
       const float* __restrict__ We,
       const int* __restrict__ e1_end,
       const int* __restrict__ e2_end,
       const float* __restrict__ te,
       float* __restrict__ z) {
    const int bx = blockIdx.x;
    const int tid = threadIdx.x;

    if (bx < NB_PF) {
        const int m = bx;
        const float* s0 = wh  + (size_t)m * H;
        const float* s1 = pe1 + (size_t)m * P;
        const float* s2 = pe2 + (size_t)m * P;
        __half* oh = g_pf_h + (size_t)m * F;
        for (int i = tid; i < F / 4; i += 256) {
            int f4 = i * 4;
            float4 x;
            if (f4 < H)            x = *(const float4*)(s0 + f4);
            else if (f4 < H + P)   x = *(const float4*)(s1 + (f4 - H));
            else                   x = *(const float4*)(s2 + (f4 - H - P));
            __half2 hh[2] = {__halves2half2(__float2half_rn(x.x), __float2half_rn(x.y)),
                             __halves2half2(__float2half_rn(x.z), __float2half_rn(x.w))};
            *(uint2*)(oh + f4) = *(uint2*)hh;
        }
        return;
    }

    if (bx < NB_PF + NB_WP) {
        __shared__ float tile[32][33];
        const int t0 = bx - NB_PF;
        const int a0 = (t0 & 15) * 32;
        const int f0 = (t0 >> 4) * 32;
        const int tx = tid & 31;
        const int ty = tid >> 5;
#pragma unroll
        for (int i = 0; i < 4; i++) {
            int f = ty + i * 8;
            tile[f][tx] = Wp[(size_t)(f0 + f) * A + a0 + tx];
        }
        __syncthreads();
#pragma unroll
        for (int i = 0; i < 4; i++) {
            int ar = ty + i * 8;
            g_wp_h[(size_t)(a0 + ar) * F + f0 + tx] = __float2half_rn(tile[tx][ar]);
        }
        return;
    }

    if (bx < NB_PF + NB_WP + NB_WE) {
        __shared__ float tile[32][33];
        const int t0 = bx - NB_PF - NB_WP;
        const int a0 = (t0 & 15) * 32;
        const int k0 = (t0 >> 4) * 32;
        const int tx = tid & 31;
        const int ty = tid >> 5;
#pragma unroll
        for (int i = 0; i < 4; i++) {
            int k = ty + i * 8;
            tile[k][tx] = We[(size_t)(k0 + k) * A + a0 + tx];
        }
        __syncthreads();
#pragma unroll
        for (int i = 0; i < 4; i++) {
            int ar = ty + i * 8;
            g_went_h[(size_t)(a0 + ar) * K_ENT + k0 + tx] = __float2half_rn(tile[tx][ar]);
        }
        return;
    }

    {
        const int b = bx - NB_PF - NB_WP - NB_WE;
        const int lane = tid & 31;
        const int wid = tid >> 5;

        __shared__ float wsum[8][16];
        __shared__ float scores[16];
        __shared__ float alpha[2][T];

        const float* h1 = wh + ((size_t)b * L + e1_end[b]) * H;
        const float* h2 = wh + ((size_t)b * L + e2_end[b]) * H;

        float s[16];
#pragma unroll
        for (int i = 0; i < 16; i++) s[i] = 0.f;
        for (int h = tid; h < H; h += 256) {
            float v1 = h1[h], v2 = h2[h];
#pragma unroll
            for (int t = 0; t < T; t++) {
                float c = te[t * H + h];
                s[t] += v1 * c;
                s[8 + t] += v2 * c;
            }
        }
#pragma unroll
        for (int off = 16; off; off >>= 1)
#pragma unroll
            for (int i = 0; i < 16; i++) s[i] += __shfl_xor_sync(0xffffffffu, s[i], off);
        if (lane == 0)
#pragma unroll
            for (int i = 0; i < 16; i++) wsum[wid][i] = s[i];
        __syncthreads();
        if (tid < 16) {
            float tot = 0.f;
#pragma unroll
            for (int w = 0; w < 8; w++) tot += wsum[w][tid];
            scores[tid] = tot;
        }
        __syncthreads();
        if (tid < 2) {
            const float* sc = scores + tid * 8;
            float m = -1e30f;
#pragma unroll
            for (int i = 0; i < T; i++) m = fmaxf(m, sc[i]);
            float sum = 0.f;
            float e[T];
#pragma unroll
            for (int i = 0; i < T; i++) { e[i] = expf(sc[i] - m); sum += e[i]; }
            float inv = 1.f / sum;
#pragma unroll
            for (int i = 0; i < T; i++) alpha[tid][i] = e[i] * inv;
        }
        __syncthreads();

        __half* ef = g_ef_h + (size_t)b * K_ENT;
        for (int h = tid; h < H; h += 256) {
            float t1 = 0.f, t2 = 0.f;
#pragma unroll
            for (int t = 0; t < T; t++) {
                float c = te[t * H + h];
                t1 += alpha[0][t] * c;
                t2 += alpha[1][t] * c;
            }
            ef[h]         = __float2half_rn(h1[h]);
            ef[H + h]     = __float2half_rn(t1);
            ef[2 * H + h] = __float2half_rn(h2[h]);
            ef[3 * H + h] = __float2half_rn(t2);
        }

#pragma unroll
        for (int q = 0; q < 4; q++) g_vu_part[q][b * L + tid] = 0.f;
        g_dense_ent[b * A + tid] = 0.f;
        g_dense_ent[b * A + 256 + tid] = 0.f;
        float4 zz = {0.f, 0.f, 0.f, 0.f};
        *(float4*)(z + (size_t)b * H + tid * 4) = zz;
    }
}

// ---------------------------------------------------------------------------
// K2 (HMMA): dense_ent = ef[64,4096] @ W_ent[4096,512], split-K=32.
// grid = (4 n-tiles of 128, 32 k-splits of 128) = 128 CTAs; 256 threads.
// ---------------------------------------------------------------------------
#define PADK2   136                      // halves per SMEM row (272 B)
__global__ void __launch_bounds__(256)
k2_dense_ent() {
    __shared__ __align__(16) __half sA[64 * PADK2];
    __shared__ __align__(16) __half sB[128 * PADK2];

    const int n0 = blockIdx.x * 128;
    const int k0 = blockIdx.y * 128;
    const int tid = threadIdx.x;
    const int lane = tid & 31;
    const int wid = tid >> 5;
    const int wm = wid >> 2;     // 0..1, m-offset 32
    const int wn = wid & 3;      // 0..3, n-offset 32

    const uint32_t sa = smem_u32(sA);
    const uint32_t sb = smem_u32(sB);

#pragma unroll
    for (int j = 0; j < 4; j++) {
        int id = tid + j * 256;
        int r = id >> 4, ch = id & 15;
        CP_ASYNC16(sa + r * (PADK2 * 2) + ch * 16,
                   g_ef_h + (size_t)r * K_ENT + k0 + ch * 8);
    }
#pragma unroll
    for (int j = 0; j < 8; j++) {
        int id = tid + j * 256;
        int r = id >> 4, ch = id & 15;
        CP_ASYNC16(sb + r * (PADK2 * 2) + ch * 16,
                   g_went_h + (size_t)(n0 + r) * K_ENT + k0 + ch * 8);
    }
    CP_COMMIT();
    CP_WAIT0();
    __syncthreads();

    float acc[2][4][4];
#pragma unroll
    for (int mt = 0; mt < 2; mt++)
#pragma unroll
        for (int nt = 0; nt < 4; nt++)
#pragma unroll
            for (int i = 0; i < 4; i++) acc[mt][nt][i] = 0.f;

#pragma unroll
    for (int kt = 0; kt < 8; kt++) {
        uint32_t ah[2][4];
        const int acol = kt * 16 + ((lane >> 4) << 3);
#pragma unroll
        for (int mt = 0; mt < 2; mt++) {
            int row = wm * 32 + mt * 16 + (lane & 15);
            LDSM4(ah[mt][0], ah[mt][1], ah[mt][2], ah[mt][3],
                  sa + row * (PADK2 * 2) + acol * 2);
        }
        const int bcol = kt * 16 + ((lane & 8) ? 8 : 0);
        const int brow_in = (lane & 7) + ((lane & 16) ? 8 : 0);
#pragma unroll
        for (int pr = 0; pr < 2; pr++) {
            int row = wn * 32 + pr * 16 + brow_in;
            uint32_t bd = sb + row * (PADK2 * 2) + bcol * 2;
            uint32_t b0[2], b1[2];
            uint32_t r0, r1, r2, r3;
            LDSM4(r0, r1, r2, r3, bd);
            b0[0] = r0; b0[1] = r1; b1[0] = r2; b1[1] = r3;
#pragma unroll
            for (int mt = 0; mt < 2; mt++) {
                MMA16816(acc[mt][pr * 2],     ah[mt], b0);
                MMA16816(acc[mt][pr * 2 + 1], ah[mt], b1);
            }
        }
    }

#pragma unroll
    for (int mt = 0; mt < 2; mt++)
#pragma unroll
        for (int h = 0; h < 2; h++) {
            const int bb = wm * 32 + mt * 16 + (lane >> 2) + h * 8;
#pragma unroll
            for (int nt = 0; nt < 4; nt++) {
                int a = n0 + wn * 32 + nt * 8 + 2 * (lane & 3);
                atomicAdd(&g_dense_ent[bb * A + a],     acc[mt][nt][2 * h]);
                atomicAdd(&g_dense_ent[bb * A + a + 1], acc[mt][nt][2 * h + 1]);
            }
        }
}

// ---------------------------------------------------------------------------
// K3: mma.sync fused GEMM + epilogue. CTA 128x128, 4 warps 64x64, 3-stage,
// 2 CTAs/SM; prefetch for t+2 issued right after the barrier (stage
// (t+2)%3 == (t-1)%3 whose readers are past the sync).
// ---------------------------------------------------------------------------
#define KT      64
#define PADK    72                      // halves per SMEM row (144 B)
#define A_SZ    (128 * PADK * 2)        // 18432 B
#define B_SZ    (128 * PADK * 2)        // 18432 B
#define OFF_A   0
#define OFF_B   (A_SZ)
#define STG_SZ  (A_SZ + B_SZ)           // 36864 B
#define NSTG    3
#define K3_DSMEM (NSTG * STG_SZ)        // 110592 B
#define NKCH    (F / KT)                // 18

__global__ void __launch_bounds__(128, 2)
k3_main(const float* __restrict__ v) {
    extern __shared__ char dsm[];
    __shared__ float sv[128];

    const int n0 = blockIdx.x * 128;
    const int m0 = blockIdx.y * 128;
    const int b  = blockIdx.y >> 1;
    const int l0 = (blockIdx.y & 1) * 128;
    const int tid = threadIdx.x;
    const int lane = tid & 31;
    const int wid = tid >> 5;     // 0..3
    const int wm = wid >> 1;      // 0..1, m-offset 64
    const int wn = wid & 1;       // 0..1, n-offset 64

    sv[tid] = v[n0 + tid];
    const uint32_t sbase = smem_u32(dsm);

    const int rr   = tid >> 3;          // 0..15
    const int ch8  = (tid & 7) * 8;
    const int ch16 = (tid & 7) * 16;
    const __half* gpA = g_pf_h + (size_t)m0 * F + ch8;
    const __half* gpB = g_wp_h + (size_t)n0 * F + ch8;

    auto load_stage = [&](int t, int stg) {
        const int f0 = t * KT;
        const uint32_t sb = sbase + stg * STG_SZ;
#pragma unroll
        for (int j = 0; j < 8; j++) {
            int r = rr + j * 16;
            CP_ASYNC16(sb + OFF_A + r * (PADK * 2) + ch16, gpA + (size_t)r * F + f0);
        }
#pragma unroll
        for (int j = 0; j < 8; j++) {
            int r = rr + j * 16;
            CP_ASYNC16(sb + OFF_B + r * (PADK * 2) + ch16, gpB + (size_t)r * F + f0);
        }
        CP_COMMIT();
    };

    float acc[4][8][4];
#pragma unroll
    for (int mt = 0; mt < 4; mt++)
#pragma unroll
        for (int nt = 0; nt < 8; nt++)
#pragma unroll
            for (int i = 0; i < 4; i++) acc[mt][nt][i] = 0.f;

    load_stage(0, 0);
    load_stage(1, 1);

    for (int t = 0; t < NKCH; t++) {
        const int s = t % NSTG;
        // groups pending: t (ours) + possibly t+1. wait until only 1 pending
        // => stage t landed. (prefetch for t+1 was issued 1 iter ago.)
        if (t + 1 < NKCH) CP_WAIT1(); else CP_WAIT0();
        __syncthreads();

        // issue t+2 NOW (target stage's last readers are behind the barrier)
        if (t + 2 < NKCH) load_stage(t + 2, (t + 2) % NSTG);

        const uint32_t st = sbase + s * STG_SZ;
#pragma unroll
        for (int kt = 0; kt < 4; kt++) {
            uint32_t ah[4][4];
            const int acol = kt * 16 + ((lane >> 4) << 3);
#pragma unroll
            for (int mt = 0; mt < 4; mt++) {
                int row = wm * 64 + mt * 16 + (lane & 15);
                LDSM4(ah[mt][0], ah[mt][1], ah[mt][2], ah[mt][3],
                      st + OFF_A + row * (PADK * 2) + acol * 2);
            }
            const int bcol = kt * 16 + ((lane & 8) ? 8 : 0);
            const int brow_in = (lane & 7) + ((lane & 16) ? 8 : 0);
#pragma unroll
            for (int pr = 0; pr < 4; pr++) {
                int row = wn * 64 + pr * 16 + brow_in;
                uint32_t bd = st + OFF_B + row * (PADK * 2) + bcol * 2;
                uint32_t b0[2], b1[2];
                uint32_t r0, r1, r2, r3;
                LDSM4(r0, r1, r2, r3, bd);
                b0[0] = r0; b0[1] = r1; b1[0] = r2; b1[1] = r3;
#pragma unroll
                for (int mt = 0; mt < 4; mt++) {
                    MMA16816(acc[mt][pr * 2],     ah[mt], b0);
                    MMA16816(acc[mt][pr * 2 + 1], ah[mt], b1);
                }
            }
        }
    }

    // ---- epilogue: tanh(acc + ent) . v, quad-reduce, atomic into quarter ---
    const int quarter = blockIdx.x;
    const int halfA = quarter >> 1;
#pragma unroll
    for (int mt = 0; mt < 4; mt++) {
#pragma unroll
        for (int h = 0; h < 2; h++) {
            const int l = l0 + wm * 64 + mt * 16 + (lane >> 2) + h * 8;
            const float e = g_dense_ent[b * A + 2 * l + halfA];
            float part = 0.f;
#pragma unroll
            for (int nt = 0; nt < 8; nt++) {
                int a = wn * 64 + nt * 8 + 2 * (lane & 3);
                part += sv[a]     * tanhf(acc[mt][nt][2 * h]     + e);
                part += sv[a + 1] * tanhf(acc[mt][nt][2 * h + 1] + e);
            }
            part += __shfl_xor_sync(0xffffffffu, part, 1);
            part += __shfl_xor_sync(0xffffffffu, part, 2);
            if ((lane & 3) == 0) atomicAdd(&g_vu_part[quarter][b * L + l], part);
        }
    }
}

// ---------------------------------------------------------------------------
// K4: softmax over L + partial z atomically into z (zeroed by k_prep).
// grid = (B, 16); 256 threads; 16 l-rows per CTA.
// ---------------------------------------------------------------------------
__global__ void __launch_bounds__(256)
k4_softmax_zp(float* __restrict__ z) {
    const int b = blockIdx.x;
    const int lq = blockIdx.y;
    const int tid = threadIdx.x;
    const int lane = tid & 31;
    const int wid = tid >> 5;

    __shared__ float sa[L];
    __shared__ float red[8];

    float vu = (g_vu_part[0][b * L + tid] + g_vu_part[1][b * L + tid])
             + (g_vu_part[2][b * L + tid] + g_vu_part[3][b * L + tid]);

    float m = vu;
#pragma unroll
    for (int off = 16; off; off >>= 1) m = fmaxf(m, __shfl_xor_sync(0xffffffffu, m, off));
    if (lane == 0) red[wid] = m;
    __syncthreads();
    if (tid < 8) {
        float mm = red[tid];
#pragma unroll
        for (int off = 4; off; off >>= 1) mm = fmaxf(mm, __shfl_xor_sync(0xffu, mm, off));
        if (tid == 0) red[0] = mm;
    }
    __syncthreads();
    const float mv = red[0];
    __syncthreads();

    float ex = expf(vu - mv);
    float ssum = ex;
#pragma unroll
    for (int off = 16; off; off >>= 1) ssum += __shfl_xor_sync(0xffffffffu, ssum, off);
    if (lane == 0) red[wid] = ssum;
    __syncthreads();
    if (tid < 8) {
        float ss = red[tid];
#pragma unroll
        for (int off = 4; off; off >>= 1) ss += __shfl_xor_sync(0xffu, ss, off);
        if (tid == 0) red[0] = ss;
    }
    __syncthreads();
    const float inv = 1.f / red[0];
    sa[tid] = ex * inv;
    __syncthreads();

    const int h4 = tid * 4;
    const __half* base = g_pf_h + ((size_t)b * L + lq * 16) * F + h4;
    float ax = 0.f, ay = 0.f, az = 0.f, aw = 0.f;
#pragma unroll
    for (int l2 = 0; l2 < 16; l2++) {
        uint2 raw = *(const uint2*)(base + (size_t)l2 * F);
        __half2 p0 = *(__half2*)&raw.x;
        __half2 p1 = *(__half2*)&raw.y;
        float2 f0 = __half22float2(p0);
        float2 f1 = __half22float2(p1);
        float s = sa[lq * 16 + l2];
        ax += s * f0.x; ay += s * f0.y; az += s * f1.x; aw += s * f1.y;
    }
    float* zb = z + (size_t)b * H + h4;
    atomicAdd(zb,     ax);
    atomicAdd(zb + 1, ay);
    atomicAdd(zb + 2, az);
    atomicAdd(zb + 3, aw);
}

// ---------------------------------------------------------------------------
extern "C" void kernel_launch(void* const* d_in, const int* in_sizes, int n_in,
                              void* d_out, int out_size) {
    const float* wh   = (const float*)d_in[0];
    const float* pe1  = (const float*)d_in[1];
    const float* pe2  = (const float*)d_in[2];
    const int*   e1e  = (const int*)d_in[3];
    const int*   e2e  = (const int*)d_in[4];
    const float* te   = (const float*)d_in[5];
    const float* Wp   = (const float*)d_in[6];
    const float* We   = (const float*)d_in[7];
    const float* v    = (const float*)d_in[8];
    float* z = (float*)d_out;

    cudaFuncSetAttribute(k3_main, cudaFuncAttributeMaxDynamicSharedMemorySize, K3_DSMEM);

    k_prep<<<NB_PF + NB_WP + NB_WE + NB_ENT, 256>>>(wh, pe1, pe2, Wp, We, e1e, e2e, te, z);
    k2_dense_ent<<<dim3(4, 32), 256>>>();
    k3_main<<<dim3(4, 128), 128, K3_DSMEM>>>(v);
    k4_softmax_zp<<<dim3(B, 16), 256>>>(z);
}

// round 16
// speedup vs baseline: 1.0872x; 1.0872x over previous
#include <cuda_runtime.h>
#include <cuda_fp16.h>
#include <math.h>
#include <stdint.h>

#define B 64
#define L 256
#define H 1024
#define P 64
#define A 512
#define T 8
#define F (H + 2 * P)   // 1152
#define M_TOT (B * L)   // 16384
#define K_ENT (4 * H)   // 4096

// ---------------- scratch (device globals; no allocation allowed) ----------
__device__ __half g_ef_h[B * K_ENT];         // entity_features fp16 [B, 4H]
__device__ __half g_went_h[A * K_ENT];       // W_ent^T fp16 [A, 4H]
__device__ float g_dense_ent[B * A];         // [B, A]
__device__ float g_vu_part[4][B * L];        // vu partials (per n-quarter)
__device__ __half g_pf_h[M_TOT * F];         // pos_features fp16 [M, F]
__device__ __half g_wp_h[A * F];             // W_pos^T fp16 [A, F]

// ---------------- helpers --------------------------------------------------
__device__ __forceinline__ uint32_t smem_u32(const void* p) {
    uint32_t a;
    asm("{ .reg .u64 t; cvta.to.shared.u64 t, %1; cvt.u32.u64 %0, t; }" : "=r"(a) : "l"(p));
    return a;
}

#define CP_ASYNC16(smem, gmem) \
    asm volatile("cp.async.cg.shared.global [%0], [%1], 16;" :: "r"(smem), "l"(gmem))
#define CP_COMMIT() asm volatile("cp.async.commit_group;" ::: "memory")
#define CP_WAIT1()  asm volatile("cp.async.wait_group 1;" ::: "memory")
#define CP_WAIT0()  asm volatile("cp.async.wait_group 0;" ::: "memory")

#define LDSM4(r0, r1, r2, r3, addr) \
    asm volatile("ldmatrix.sync.aligned.m8n8.x4.shared.b16 {%0,%1,%2,%3}, [%4];" \
        : "=r"(r0), "=r"(r1), "=r"(r2), "=r"(r3) : "r"(addr))

#define MMA16816(d, a, bb) \
    asm volatile("mma.sync.aligned.m16n8k16.row.col.f32.f16.f16.f32 " \
        "{%0,%1,%2,%3}, {%4,%5,%6,%7}, {%8,%9}, {%0,%1,%2,%3};" \
        : "+f"((d)[0]), "+f"((d)[1]), "+f"((d)[2]), "+f"((d)[3]) \
        : "r"((a)[0]), "r"((a)[1]), "r"((a)[2]), "r"((a)[3]), "r"((bb)[0]), "r"((bb)[1]))

// ---------------------------------------------------------------------------
// K_PREP: fused pf->fp16, W_pos^T->fp16, W_ent^T->fp16, entity prep + zeroing.
// grid = 16384 + 576 + 2048 + 64 = 19072 CTAs; 256 threads.
// ---------------------------------------------------------------------------
#define NB_PF  M_TOT
#define NB_WP  ((A / 32) * (F / 32))      // 576
#define NB_WE  ((A / 32) * (K_ENT / 32))  // 2048
#define NB_ENT B

__global__ void __launch_bounds__(256)
k_prep(const float* __restrict__ wh,
       const float* __restrict__ pe1,
       const float* __restrict__ pe2,
       const float* __restrict__ Wp,
       const float* __restrict__ We,
       const int* __restrict__ e1_end,
       const int* __restrict__ e2_end,
       const float* __restrict__ te,
       float* __restrict__ z) {
    const int bx = blockIdx.x;
    const int tid = threadIdx.x;

    if (bx < NB_PF) {
        const int m = bx;
        const float* s0 = wh  + (size_t)m * H;
        const float* s1 = pe1 + (size_t)m * P;
        const float* s2 = pe2 + (size_t)m * P;
        __half* oh = g_pf_h + (size_t)m * F;
        for (int i = tid; i < F / 4; i += 256) {
            int f4 = i * 4;
            float4 x;
            if (f4 < H)            x = *(const float4*)(s0 + f4);
            else if (f4 < H + P)   x = *(const float4*)(s1 + (f4 - H));
            else                   x = *(const float4*)(s2 + (f4 - H - P));
            __half2 hh[2] = {__halves2half2(__float2half_rn(x.x), __float2half_rn(x.y)),
                             __halves2half2(__float2half_rn(x.z), __float2half_rn(x.w))};
            *(uint2*)(oh + f4) = *(uint2*)hh;
        }
        return;
    }

    if (bx < NB_PF + NB_WP) {
        __shared__ float tile[32][33];
        const int t0 = bx - NB_PF;
        const int a0 = (t0 & 15) * 32;
        const int f0 = (t0 >> 4) * 32;
        const int tx = tid & 31;
        const int ty = tid >> 5;
#pragma unroll
        for (int i = 0; i < 4; i++) {
            int f = ty + i * 8;
            tile[f][tx] = Wp[(size_t)(f0 + f) * A + a0 + tx];
        }
        __syncthreads();
#pragma unroll
        for (int i = 0; i < 4; i++) {
            int ar = ty + i * 8;
            g_wp_h[(size_t)(a0 + ar) * F + f0 + tx] = __float2half_rn(tile[tx][ar]);
        }
        return;
    }

    if (bx < NB_PF + NB_WP + NB_WE) {
        __shared__ float tile[32][33];
        const int t0 = bx - NB_PF - NB_WP;
        const int a0 = (t0 & 15) * 32;
        const int k0 = (t0 >> 4) * 32;
        const int tx = tid & 31;
        const int ty = tid >> 5;
#pragma unroll
        for (int i = 0; i < 4; i++) {
            int k = ty + i * 8;
            tile[k][tx] = We[(size_t)(k0 + k) * A + a0 + tx];
        }
        __syncthreads();
#pragma unroll
        for (int i = 0; i < 4; i++) {
            int ar = ty + i * 8;
            g_went_h[(size_t)(a0 + ar) * K_ENT + k0 + tx] = __float2half_rn(tile[tx][ar]);
        }
        return;
    }

    {
        const int b = bx - NB_PF - NB_WP - NB_WE;
        const int lane = tid & 31;
        const int wid = tid >> 5;

        __shared__ float wsum[8][16];
        __shared__ float scores[16];
        __shared__ float alpha[2][T];

        const float* h1 = wh + ((size_t)b * L + e1_end[b]) * H;
        const float* h2 = wh + ((size_t)b * L + e2_end[b]) * H;

        float s[16];
#pragma unroll
        for (int i = 0; i < 16; i++) s[i] = 0.f;
        for (int h = tid; h < H; h += 256) {
            float v1 = h1[h], v2 = h2[h];
#pragma unroll
            for (int t = 0; t < T; t++) {
                float c = te[t * H + h];
                s[t] += v1 * c;
                s[8 + t] += v2 * c;
            }
        }
#pragma unroll
        for (int off = 16; off; off >>= 1)
#pragma unroll
            for (int i = 0; i < 16; i++) s[i] += __shfl_xor_sync(0xffffffffu, s[i], off);
        if (lane == 0)
#pragma unroll
            for (int i = 0; i < 16; i++) wsum[wid][i] = s[i];
        __syncthreads();
        if (tid < 16) {
            float tot = 0.f;
#pragma unroll
            for (int w = 0; w < 8; w++) tot += wsum[w][tid];
            scores[tid] = tot;
        }
        __syncthreads();
        if (tid < 2) {
            const float* sc = scores + tid * 8;
            float m = -1e30f;
#pragma unroll
            for (int i = 0; i < T; i++) m = fmaxf(m, sc[i]);
            float sum = 0.f;
            float e[T];
#pragma unroll
            for (int i = 0; i < T; i++) { e[i] = expf(sc[i] - m); sum += e[i]; }
            float inv = 1.f / sum;
#pragma unroll
            for (int i = 0; i < T; i++) alpha[tid][i] = e[i] * inv;
        }
        __syncthreads();

        __half* ef = g_ef_h + (size_t)b * K_ENT;
        for (int h = tid; h < H; h += 256) {
            float t1 = 0.f, t2 = 0.f;
#pragma unroll
            for (int t = 0; t < T; t++) {
                float c = te[t * H + h];
                t1 += alpha[0][t] * c;
                t2 += alpha[1][t] * c;
            }
            ef[h]         = __float2half_rn(h1[h]);
            ef[H + h]     = __float2half_rn(t1);
            ef[2 * H + h] = __float2half_rn(h2[h]);
            ef[3 * H + h] = __float2half_rn(t2);
        }

        g_dense_ent[b * A + tid] = 0.f;
        g_dense_ent[b * A + 256 + tid] = 0.f;
        float4 zz = {0.f, 0.f, 0.f, 0.f};
        *(float4*)(z + (size_t)b * H + tid * 4) = zz;
    }
}

// ---------------------------------------------------------------------------
// K2 (HMMA): dense_ent = ef[64,4096] @ W_ent[4096,512], split-K=32.
// grid = (4 n-tiles of 128, 32 k-splits of 128) = 128 CTAs; 256 threads.
// ---------------------------------------------------------------------------
#define PADK2   136                      // halves per SMEM row (272 B)
__global__ void __launch_bounds__(256)
k2_dense_ent() {
    __shared__ __align__(16) __half sA[64 * PADK2];
    __shared__ __align__(16) __half sB[128 * PADK2];

    const int n0 = blockIdx.x * 128;
    const int k0 = blockIdx.y * 128;
    const int tid = threadIdx.x;
    const int lane = tid & 31;
    const int wid = tid >> 5;
    const int wm = wid >> 2;     // 0..1, m-offset 32
    const int wn = wid & 3;      // 0..3, n-offset 32

    const uint32_t sa = smem_u32(sA);
    const uint32_t sb = smem_u32(sB);

#pragma unroll
    for (int j = 0; j < 4; j++) {
        int id = tid + j * 256;
        int r = id >> 4, ch = id & 15;
        CP_ASYNC16(sa + r * (PADK2 * 2) + ch * 16,
                   g_ef_h + (size_t)r * K_ENT + k0 + ch * 8);
    }
#pragma unroll
    for (int j = 0; j < 8; j++) {
        int id = tid + j * 256;
        int r = id >> 4, ch = id & 15;
        CP_ASYNC16(sb + r * (PADK2 * 2) + ch * 16,
                   g_went_h + (size_t)(n0 + r) * K_ENT + k0 + ch * 8);
    }
    CP_COMMIT();
    CP_WAIT0();
    __syncthreads();

    float acc[2][4][4];
#pragma unroll
    for (int mt = 0; mt < 2; mt++)
#pragma unroll
        for (int nt = 0; nt < 4; nt++)
#pragma unroll
            for (int i = 0; i < 4; i++) acc[mt][nt][i] = 0.f;

#pragma unroll
    for (int kt = 0; kt < 8; kt++) {
        uint32_t ah[2][4];
        const int acol = kt * 16 + ((lane >> 4) << 3);
#pragma unroll
        for (int mt = 0; mt < 2; mt++) {
            int row = wm * 32 + mt * 16 + (lane & 15);
            LDSM4(ah[mt][0], ah[mt][1], ah[mt][2], ah[mt][3],
                  sa + row * (PADK2 * 2) + acol * 2);
        }
        const int bcol = kt * 16 + ((lane & 8) ? 8 : 0);
        const int brow_in = (lane & 7) + ((lane & 16) ? 8 : 0);
#pragma unroll
        for (int pr = 0; pr < 2; pr++) {
            int row = wn * 32 + pr * 16 + brow_in;
            uint32_t bd = sb + row * (PADK2 * 2) + bcol * 2;
            uint32_t b0[2], b1[2];
            uint32_t r0, r1, r2, r3;
            LDSM4(r0, r1, r2, r3, bd);
            b0[0] = r0; b0[1] = r1; b1[0] = r2; b1[1] = r3;
#pragma unroll
            for (int mt = 0; mt < 2; mt++) {
                MMA16816(acc[mt][pr * 2],     ah[mt], b0);
                MMA16816(acc[mt][pr * 2 + 1], ah[mt], b1);
            }
        }
    }

#pragma unroll
    for (int mt = 0; mt < 2; mt++)
#pragma unroll
        for (int h = 0; h < 2; h++) {
            const int bb = wm * 32 + mt * 16 + (lane >> 2) + h * 8;
#pragma unroll
            for (int nt = 0; nt < 4; nt++) {
                int a = n0 + wn * 32 + nt * 8 + 2 * (lane & 3);
                atomicAdd(&g_dense_ent[bb * A + a],     acc[mt][nt][2 * h]);
                atomicAdd(&g_dense_ent[bb * A + a + 1], acc[mt][nt][2 * h + 1]);
            }
        }
}

// ---------------------------------------------------------------------------
// K3 (R14 structure): mma.sync fused GEMM + atomic-free epilogue.
// CTA 128x128, 128 threads = 4 warps (2m x 2n), warp tile 64x64; 3-stage,
// compute-then-prefetch order (measured best); 2 CTAs/SM; grid (4, 128).
// Epilogue: the two n-half warps combine through smem, plain store to vu_part.
// ---------------------------------------------------------------------------
#define KT      64
#define PADK    72                      // halves per SMEM row (144 B)
#define A_SZ    (128 * PADK * 2)        // 18432 B
#define B_SZ    (128 * PADK * 2)        // 18432 B
#define OFF_A   0
#define OFF_B   (A_SZ)
#define STG_SZ  (A_SZ + B_SZ)           // 36864 B
#define NSTG    3
#define K3_DSMEM (NSTG * STG_SZ)        // 110592 B
#define NKCH    (F / KT)                // 18

__global__ void __launch_bounds__(128, 2)
k3_main(const float* __restrict__ v) {
    extern __shared__ char dsm[];
    __shared__ float sv[128];
    __shared__ float s_red[2][4][2][8];   // [wm][mt][h][row-in-8]

    const int n0 = blockIdx.x * 128;
    const int m0 = blockIdx.y * 128;
    const int b  = blockIdx.y >> 1;
    const int l0 = (blockIdx.y & 1) * 128;
    const int tid = threadIdx.x;
    const int lane = tid & 31;
    const int wid = tid >> 5;     // 0..3
    const int wm = wid >> 1;      // 0..1, m-offset 64
    const int wn = wid & 1;       // 0..1, n-offset 64

    sv[tid] = v[n0 + tid];
    const uint32_t sbase = smem_u32(dsm);

    const int rr   = tid >> 3;          // 0..15
    const int ch8  = (tid & 7) * 8;
    const int ch16 = (tid & 7) * 16;
    const __half* gpA = g_pf_h + (size_t)m0 * F + ch8;
    const __half* gpB = g_wp_h + (size_t)n0 * F + ch8;

    auto load_stage = [&](int t, int stg) {
        const int f0 = t * KT;
        const uint32_t sb = sbase + stg * STG_SZ;
#pragma unroll
        for (int j = 0; j < 8; j++) {
            int r = rr + j * 16;
            CP_ASYNC16(sb + OFF_A + r * (PADK * 2) + ch16, gpA + (size_t)r * F + f0);
        }
#pragma unroll
        for (int j = 0; j < 8; j++) {
            int r = rr + j * 16;
            CP_ASYNC16(sb + OFF_B + r * (PADK * 2) + ch16, gpB + (size_t)r * F + f0);
        }
        CP_COMMIT();
    };

    float acc[4][8][4];
#pragma unroll
    for (int mt = 0; mt < 4; mt++)
#pragma unroll
        for (int nt = 0; nt < 8; nt++)
#pragma unroll
            for (int i = 0; i < 4; i++) acc[mt][nt][i] = 0.f;

    load_stage(0, 0);
    load_stage(1, 1);

    for (int t = 0; t < NKCH; t++) {
        const int s = t % NSTG;
        if (t + 1 < NKCH) CP_WAIT1(); else CP_WAIT0();
        __syncthreads();

        const uint32_t st = sbase + s * STG_SZ;
#pragma unroll
        for (int kt = 0; kt < 4; kt++) {
            uint32_t ah[4][4];
            const int acol = kt * 16 + ((lane >> 4) << 3);
#pragma unroll
            for (int mt = 0; mt < 4; mt++) {
                int row = wm * 64 + mt * 16 + (lane & 15);
                LDSM4(ah[mt][0], ah[mt][1], ah[mt][2], ah[mt][3],
                      st + OFF_A + row * (PADK * 2) + acol * 2);
            }
            const int bcol = kt * 16 + ((lane & 8) ? 8 : 0);
            const int brow_in = (lane & 7) + ((lane & 16) ? 8 : 0);
#pragma unroll
            for (int pr = 0; pr < 4; pr++) {
                int row = wn * 64 + pr * 16 + brow_in;
                uint32_t bd = st + OFF_B + row * (PADK * 2) + bcol * 2;
                uint32_t b0[2], b1[2];
                uint32_t r0, r1, r2, r3;
                LDSM4(r0, r1, r2, r3, bd);
                b0[0] = r0; b0[1] = r1; b1[0] = r2; b1[1] = r3;
#pragma unroll
                for (int mt = 0; mt < 4; mt++) {
                    MMA16816(acc[mt][pr * 2],     ah[mt], b0);
                    MMA16816(acc[mt][pr * 2 + 1], ah[mt], b1);
                }
            }
        }

        if (t + 2 < NKCH) load_stage(t + 2, (t + 2) % NSTG);
    }

    // ---- epilogue: tanh(acc + ent) . v, quad-reduce, smem-combine, store ---
    const int quarter = blockIdx.x;
    const int halfA = quarter >> 1;
    float part[4][2];
#pragma unroll
    for (int mt = 0; mt < 4; mt++) {
#pragma unroll
        for (int h = 0; h < 2; h++) {
            const int l = l0 + wm * 64 + mt * 16 + (lane >> 2) + h * 8;
            const float e = g_dense_ent[b * A + 2 * l + halfA];
            float p = 0.f;
#pragma unroll
            for (int nt = 0; nt < 8; nt++) {
                int a = wn * 64 + nt * 8 + 2 * (lane & 3);
                p += sv[a]     * tanhf(acc[mt][nt][2 * h]     + e);
                p += sv[a + 1] * tanhf(acc[mt][nt][2 * h + 1] + e);
            }
            p += __shfl_xor_sync(0xffffffffu, p, 1);
            p += __shfl_xor_sync(0xffffffffu, p, 2);
            part[mt][h] = p;
            if (wn == 0 && (lane & 3) == 0)
                s_red[wm][mt][h][lane >> 2] = p;
        }
    }
    __syncthreads();
    if (wn == 1 && (lane & 3) == 0) {
#pragma unroll
        for (int mt = 0; mt < 4; mt++)
#pragma unroll
            for (int h = 0; h < 2; h++) {
                const int l = l0 + wm * 64 + mt * 16 + (lane >> 2) + h * 8;
                g_vu_part[quarter][b * L + l] =
                    part[mt][h] + s_red[wm][mt][h][lane >> 2];
            }
    }
}

// ---------------------------------------------------------------------------
// K4: softmax over L + partial z atomically into z (zeroed by k_prep).
// grid = (B, 8); 256 threads; 32 l-rows per CTA. (measured best config)
// ---------------------------------------------------------------------------
__global__ void __launch_bounds__(256)
k4_softmax_zp(float* __restrict__ z) {
    const int b = blockIdx.x;
    const int lq = blockIdx.y;
    const int tid = threadIdx.x;
    const int lane = tid & 31;
    const int wid = tid >> 5;

    __shared__ float sa[L];
    __shared__ float red[8];

    float vu = (g_vu_part[0][b * L + tid] + g_vu_part[1][b * L + tid])
             + (g_vu_part[2][b * L + tid] + g_vu_part[3][b * L + tid]);

    float m = vu;
#pragma unroll
    for (int off = 16; off; off >>= 1) m = fmaxf(m, __shfl_xor_sync(0xffffffffu, m, off));
    if (lane == 0) red[wid] = m;
    __syncthreads();
    if (tid < 8) {
        float mm = red[tid];
#pragma unroll
        for (int off = 4; off; off >>= 1) mm = fmaxf(mm, __shfl_xor_sync(0xffu, mm, off));
        if (tid == 0) red[0] = mm;
    }
    __syncthreads();
    const float mv = red[0];
    __syncthreads();

    float ex = expf(vu - mv);
    float ssum = ex;
#pragma unroll
    for (int off = 16; off; off >>= 1) ssum += __shfl_xor_sync(0xffffffffu, ssum, off);
    if (lane == 0) red[wid] = ssum;
    __syncthreads();
    if (tid < 8) {
        float ss = red[tid];
#pragma unroll
        for (int off = 4; off; off >>= 1) ss += __shfl_xor_sync(0xffu, ss, off);
        if (tid == 0) red[0] = ss;
    }
    __syncthreads();
    const float inv = 1.f / red[0];
    sa[tid] = ex * inv;
    __syncthreads();

    const int h4 = tid * 4;
    const __half* base = g_pf_h + ((size_t)b * L + lq * 32) * F + h4;
    float ax = 0.f, ay = 0.f, az = 0.f, aw = 0.f;
#pragma unroll
    for (int l2 = 0; l2 < 32; l2++) {
        uint2 raw = *(const uint2*)(base + (size_t)l2 * F);
        __half2 p0 = *(__half2*)&raw.x;
        __half2 p1 = *(__half2*)&raw.y;
        float2 f0 = __half22float2(p0);
        float2 f1 = __half22float2(p1);
        float s = sa[lq * 32 + l2];
        ax += s * f0.x; ay += s * f0.y; az += s * f1.x; aw += s * f1.y;
    }
    float* zb = z + (size_t)b * H + h4;
    atomicAdd(zb,     ax);
    atomicAdd(zb + 1, ay);
    atomicAdd(zb + 2, az);
    atomicAdd(zb + 3, aw);
}

// ---------------------------------------------------------------------------
extern "C" void kernel_launch(void* const* d_in, const int* in_sizes, int n_in,
                              void* d_out, int out_size) {
    const float* wh   = (const float*)d_in[0];
    const float* pe1  = (const float*)d_in[1];
    const float* pe2  = (const float*)d_in[2];
    const int*   e1e  = (const int*)d_in[3];
    const int*   e2e  = (const int*)d_in[4];
    const float* te   = (const float*)d_in[5];
    const float* Wp   = (const float*)d_in[6];
    const float* We   = (const float*)d_in[7];
    const float* v    = (const float*)d_in[8];
    float* z = (float*)d_out;

    cudaFuncSetAttribute(k3_main, cudaFuncAttributeMaxDynamicSharedMemorySize, K3_DSMEM);

    k_prep<<<NB_PF + NB_WP + NB_WE + NB_ENT, 256>>>(wh, pe1, pe2, Wp, We, e1e, e2e, te, z);
    k2_dense_ent<<<dim3(4, 32), 256>>>();
    k3_main<<<dim3(4, 128), 128, K3_DSMEM>>>(v);
    k4_softmax_zp<<<dim3(B, 8), 256>>>(z);
}

// round 17
// speedup vs baseline: 1.0876x; 1.0003x over previous
#include <cuda_runtime.h>
#include <cuda_fp16.h>
#include <math.h>
#include <stdint.h>

#define B 64
#define L 256
#define H 1024
#define P 64
#define A 512
#define T 8
#define F (H + 2 * P)   // 1152
#define M_TOT (B * L)   // 16384
#define K_ENT (4 * H)   // 4096

// ---------------- scratch (device globals; no allocation allowed) ----------
__device__ __half g_ef_h[B * K_ENT];         // entity_features fp16 [B, 4H]
__device__ __half g_went_h[A * K_ENT];       // W_ent^T fp16 [A, 4H]
__device__ float g_dense_ent[B * A];         // [B, A]
__device__ float g_vu_part[4][B * L];        // vu partials (per n-quarter)
__device__ __half g_pf_h[M_TOT * F];         // pos_features fp16 [M, F]
__device__ __half g_wp_h[A * F];             // W_pos^T fp16 [A, F]

// ---------------- helpers --------------------------------------------------
__device__ __forceinline__ uint32_t smem_u32(const void* p) {
    uint32_t a;
    asm("{ .reg .u64 t; cvta.to.shared.u64 t, %1; cvt.u32.u64 %0, t; }" : "=r"(a) : "l"(p));
    return a;
}

#define CP_ASYNC16(smem, gmem) \
    asm volatile("cp.async.cg.shared.global [%0], [%1], 16;" :: "r"(smem), "l"(gmem))
#define CP_COMMIT() asm volatile("cp.async.commit_group;" ::: "memory")
#define CP_WAIT1()  asm volatile("cp.async.wait_group 1;" ::: "memory")
#define CP_WAIT0()  asm volatile("cp.async.wait_group 0;" ::: "memory")

#define LDSM4(r0, r1, r2, r3, addr) \
    asm volatile("ldmatrix.sync.aligned.m8n8.x4.shared.b16 {%0,%1,%2,%3}, [%4];" \
        : "=r"(r0), "=r"(r1), "=r"(r2), "=r"(r3) : "r"(addr))

#define MMA16816(d, a, bb) \
    asm volatile("mma.sync.aligned.m16n8k16.row.col.f32.f16.f16.f32 " \
        "{%0,%1,%2,%3}, {%4,%5,%6,%7}, {%8,%9}, {%0,%1,%2,%3};" \
        : "+f"((d)[0]), "+f"((d)[1]), "+f"((d)[2]), "+f"((d)[3]) \
        : "r"((a)[0]), "r"((a)[1]), "r"((a)[2]), "r"((a)[3]), "r"((bb)[0]), "r"((bb)[1]))

// ---------------------------------------------------------------------------
// K_PREP: fused pf->fp16, W_pos^T->fp16, W_ent^T->fp16, entity prep + zeroing.
// grid = 16384 + 576 + 2048 + 64 = 19072 CTAs; 256 threads.
// ---------------------------------------------------------------------------
#define NB_PF  M_TOT
#define NB_WP  ((A / 32) * (F / 32))      // 576
#define NB_WE  ((A / 32) * (K_ENT / 32))  // 2048
#define NB_ENT B

__global__ void __launch_bounds__(256)
k_prep(const float* __restrict__ wh,
       const float* __restrict__ pe1,
       const float* __restrict__ pe2,
       const float* __restrict__ Wp,
       const float* __restrict__ We,
       const int* __restrict__ e1_end,
       const int* __restrict__ e2_end,
       const float* __restrict__ te,
       float* __restrict__ z) {
    const int bx = blockIdx.x;
    const int tid = threadIdx.x;

    if (bx < NB_PF) {
        const int m = bx;
        const float* s0 = wh  + (size_t)m * H;
        const float* s1 = pe1 + (size_t)m * P;
        const float* s2 = pe2 + (size_t)m * P;
        __half* oh = g_pf_h + (size_t)m * F;
        for (int i = tid; i < F / 4; i += 256) {
            int f4 = i * 4;
            float4 x;
            if (f4 < H)            x = *(const float4*)(s0 + f4);
            else if (f4 < H + P)   x = *(const float4*)(s1 + (f4 - H));
            else                   x = *(const float4*)(s2 + (f4 - H - P));
            __half2 hh[2] = {__halves2half2(__float2half_rn(x.x), __float2half_rn(x.y)),
                             __halves2half2(__float2half_rn(x.z), __float2half_rn(x.w))};
            *(uint2*)(oh + f4) = *(uint2*)hh;
        }
        return;
    }

    if (bx < NB_PF + NB_WP) {
        __shared__ float tile[32][33];
        const int t0 = bx - NB_PF;
        const int a0 = (t0 & 15) * 32;
        const int f0 = (t0 >> 4) * 32;
        const int tx = tid & 31;
        const int ty = tid >> 5;
#pragma unroll
        for (int i = 0; i < 4; i++) {
            int f = ty + i * 8;
            tile[f][tx] = Wp[(size_t)(f0 + f) * A + a0 + tx];
        }
        __syncthreads();
#pragma unroll
        for (int i = 0; i < 4; i++) {
            int ar = ty + i * 8;
            g_wp_h[(size_t)(a0 + ar) * F + f0 + tx] = __float2half_rn(tile[tx][ar]);
        }
        return;
    }

    if (bx < NB_PF + NB_WP + NB_WE) {
        __shared__ float tile[32][33];
        const int t0 = bx - NB_PF - NB_WP;
        const int a0 = (t0 & 15) * 32;
        const int k0 = (t0 >> 4) * 32;
        const int tx = tid & 31;
        const int ty = tid >> 5;
#pragma unroll
        for (int i = 0; i < 4; i++) {
            int k = ty + i * 8;
            tile[k][tx] = We[(size_t)(k0 + k) * A + a0 + tx];
        }
        __syncthreads();
#pragma unroll
        for (int i = 0; i < 4; i++) {
            int ar = ty + i * 8;
            g_went_h[(size_t)(a0 + ar) * K_ENT + k0 + tx] = __float2half_rn(tile[tx][ar]);
        }
        return;
    }

    {
        const int b = bx - NB_PF - NB_WP - NB_WE;
        const int lane = tid & 31;
        const int wid = tid >> 5;

        __shared__ float wsum[8][16];
        __shared__ float scores[16];
        __shared__ float alpha[2][T];

        const float* h1 = wh + ((size_t)b * L + e1_end[b]) * H;
        const float* h2 = wh + ((size_t)b * L + e2_end[b]) * H;

        float s[16];
#pragma unroll
        for (int i = 0; i < 16; i++) s[i] = 0.f;
        for (int h = tid; h < H; h += 256) {
            float v1 = h1[h], v2 = h2[h];
#pragma unroll
            for (int t = 0; t < T; t++) {
                float c = te[t * H + h];
                s[t] += v1 * c;
                s[8 + t] += v2 * c;
            }
        }
#pragma unroll
        for (int off = 16; off; off >>= 1)
#pragma unroll
            for (int i = 0; i < 16; i++) s[i] += __shfl_xor_sync(0xffffffffu, s[i], off);
        if (lane == 0)
#pragma unroll
            for (int i = 0; i < 16; i++) wsum[wid][i] = s[i];
        __syncthreads();
        if (tid < 16) {
            float tot = 0.f;
#pragma unroll
            for (int w = 0; w < 8; w++) tot += wsum[w][tid];
            scores[tid] = tot;
        }
        __syncthreads();
        if (tid < 2) {
            const float* sc = scores + tid * 8;
            float m = -1e30f;
#pragma unroll
            for (int i = 0; i < T; i++) m = fmaxf(m, sc[i]);
            float sum = 0.f;
            float e[T];
#pragma unroll
            for (int i = 0; i < T; i++) { e[i] = expf(sc[i] - m); sum += e[i]; }
            float inv = 1.f / sum;
#pragma unroll
            for (int i = 0; i < T; i++) alpha[tid][i] = e[i] * inv;
        }
        __syncthreads();

        __half* ef = g_ef_h + (size_t)b * K_ENT;
        for (int h = tid; h < H; h += 256) {
            float t1 = 0.f, t2 = 0.f;
#pragma unroll
            for (int t = 0; t < T; t++) {
                float c = te[t * H + h];
                t1 += alpha[0][t] * c;
                t2 += alpha[1][t] * c;
            }
            ef[h]         = __float2half_rn(h1[h]);
            ef[H + h]     = __float2half_rn(t1);
            ef[2 * H + h] = __float2half_rn(h2[h]);
            ef[3 * H + h] = __float2half_rn(t2);
        }

        g_dense_ent[b * A + tid] = 0.f;
        g_dense_ent[b * A + 256 + tid] = 0.f;
        float4 zz = {0.f, 0.f, 0.f, 0.f};
        *(float4*)(z + (size_t)b * H + tid * 4) = zz;
    }
}

// ---------------------------------------------------------------------------
// K2 (HMMA): dense_ent = ef[64,4096] @ W_ent[4096,512], split-K=32.
// grid = (4 n-tiles of 128, 32 k-splits of 128) = 128 CTAs; 256 threads.
// ---------------------------------------------------------------------------
#define PADK2   136                      // halves per SMEM row (272 B)
__global__ void __launch_bounds__(256)
k2_dense_ent() {
    __shared__ __align__(16) __half sA[64 * PADK2];
    __shared__ __align__(16) __half sB[128 * PADK2];

    const int n0 = blockIdx.x * 128;
    const int k0 = blockIdx.y * 128;
    const int tid = threadIdx.x;
    const int lane = tid & 31;
    const int wid = tid >> 5;
    const int wm = wid >> 2;     // 0..1, m-offset 32
    const int wn = wid & 3;      // 0..3, n-offset 32

    const uint32_t sa = smem_u32(sA);
    const uint32_t sb = smem_u32(sB);

#pragma unroll
    for (int j = 0; j < 4; j++) {
        int id = tid + j * 256;
        int r = id >> 4, ch = id & 15;
        CP_ASYNC16(sa + r * (PADK2 * 2) + ch * 16,
                   g_ef_h + (size_t)r * K_ENT + k0 + ch * 8);
    }
#pragma unroll
    for (int j = 0; j < 8; j++) {
        int id = tid + j * 256;
        int r = id >> 4, ch = id & 15;
        CP_ASYNC16(sb + r * (PADK2 * 2) + ch * 16,
                   g_went_h + (size_t)(n0 + r) * K_ENT + k0 + ch * 8);
    }
    CP_COMMIT();
    CP_WAIT0();
    __syncthreads();

    float acc[2][4][4];
#pragma unroll
    for (int mt = 0; mt < 2; mt++)
#pragma unroll
        for (int nt = 0; nt < 4; nt++)
#pragma unroll
            for (int i = 0; i < 4; i++) acc[mt][nt][i] = 0.f;

#pragma unroll
    for (int kt = 0; kt < 8; kt++) {
        uint32_t ah[2][4];
        const int acol = kt * 16 + ((lane >> 4) << 3);
#pragma unroll
        for (int mt = 0; mt < 2; mt++) {
            int row = wm * 32 + mt * 16 + (lane & 15);
            LDSM4(ah[mt][0], ah[mt][1], ah[mt][2], ah[mt][3],
                  sa + row * (PADK2 * 2) + acol * 2);
        }
        const int bcol = kt * 16 + ((lane & 8) ? 8 : 0);
        const int brow_in = (lane & 7) + ((lane & 16) ? 8 : 0);
#pragma unroll
        for (int pr = 0; pr < 2; pr++) {
            int row = wn * 32 + pr * 16 + brow_in;
            uint32_t bd = sb + row * (PADK2 * 2) + bcol * 2;
            uint32_t b0[2], b1[2];
            uint32_t r0, r1, r2, r3;
            LDSM4(r0, r1, r2, r3, bd);
            b0[0] = r0; b0[1] = r1; b1[0] = r2; b1[1] = r3;
#pragma unroll
            for (int mt = 0; mt < 2; mt++) {
                MMA16816(acc[mt][pr * 2],     ah[mt], b0);
                MMA16816(acc[mt][pr * 2 + 1], ah[mt], b1);
            }
        }
    }

#pragma unroll
    for (int mt = 0; mt < 2; mt++)
#pragma unroll
        for (int h = 0; h < 2; h++) {
            const int bb = wm * 32 + mt * 16 + (lane >> 2) + h * 8;
#pragma unroll
            for (int nt = 0; nt < 4; nt++) {
                int a = n0 + wn * 32 + nt * 8 + 2 * (lane & 3);
                atomicAdd(&g_dense_ent[bb * A + a],     acc[mt][nt][2 * h]);
                atomicAdd(&g_dense_ent[bb * A + a + 1], acc[mt][nt][2 * h + 1]);
            }
        }
}

// ---------------------------------------------------------------------------
// K3: mma.sync fused GEMM + atomic-free epilogue, REGISTER-PIPELINED kt loop.
// CTA 128x128, 128 threads = 4 warps (2m x 2n), warp tile 64x64; 3-stage
// cp.async (compute-then-prefetch); 2 CTAs/SM; grid (4, 128).
// Fragments for kt+1 are LDSM'd while kt's 32 MMAs execute (double buffer).
// ---------------------------------------------------------------------------
#define KT      64
#define PADK    72                      // halves per SMEM row (144 B)
#define A_SZ    (128 * PADK * 2)        // 18432 B
#define B_SZ    (128 * PADK * 2)        // 18432 B
#define OFF_A   0
#define OFF_B   (A_SZ)
#define STG_SZ  (A_SZ + B_SZ)           // 36864 B
#define NSTG    3
#define K3_DSMEM (NSTG * STG_SZ)        // 110592 B
#define NKCH    (F / KT)                // 18

__global__ void __launch_bounds__(128, 2)
k3_main(const float* __restrict__ v) {
    extern __shared__ char dsm[];
    __shared__ float sv[128];
    __shared__ float s_red[2][4][2][8];   // [wm][mt][h][row-in-8]

    const int n0 = blockIdx.x * 128;
    const int m0 = blockIdx.y * 128;
    const int b  = blockIdx.y >> 1;
    const int l0 = (blockIdx.y & 1) * 128;
    const int tid = threadIdx.x;
    const int lane = tid & 31;
    const int wid = tid >> 5;     // 0..3
    const int wm = wid >> 1;      // 0..1, m-offset 64
    const int wn = wid & 1;       // 0..1, n-offset 64

    sv[tid] = v[n0 + tid];
    const uint32_t sbase = smem_u32(dsm);

    const int rr   = tid >> 3;          // 0..15
    const int ch8  = (tid & 7) * 8;
    const int ch16 = (tid & 7) * 16;
    const __half* gpA = g_pf_h + (size_t)m0 * F + ch8;
    const __half* gpB = g_wp_h + (size_t)n0 * F + ch8;

    auto load_stage = [&](int t, int stg) {
        const int f0 = t * KT;
        const uint32_t sb = sbase + stg * STG_SZ;
#pragma unroll
        for (int j = 0; j < 8; j++) {
            int r = rr + j * 16;
            CP_ASYNC16(sb + OFF_A + r * (PADK * 2) + ch16, gpA + (size_t)r * F + f0);
        }
#pragma unroll
        for (int j = 0; j < 8; j++) {
            int r = rr + j * 16;
            CP_ASYNC16(sb + OFF_B + r * (PADK * 2) + ch16, gpB + (size_t)r * F + f0);
        }
        CP_COMMIT();
    };

    float acc[4][8][4];
#pragma unroll
    for (int mt = 0; mt < 4; mt++)
#pragma unroll
        for (int nt = 0; nt < 8; nt++)
#pragma unroll
            for (int i = 0; i < 4; i++) acc[mt][nt][i] = 0.f;

    load_stage(0, 0);
    load_stage(1, 1);

    // fragment geometry (kt-invariant parts)
    const int arow_base = wm * 64 + (lane & 15);
    const int acol_sub  = (lane >> 4) << 3;
    const int bcol_sub  = (lane & 8) ? 8 : 0;
    const int brow_in   = (lane & 7) + ((lane & 16) ? 8 : 0);

    uint32_t ah[2][4][4];    // [buf][mt][frag]
    uint32_t bf[2][4][4];    // [buf][pr][frag]

    for (int t = 0; t < NKCH; t++) {
        const int s = t % NSTG;
        if (t + 1 < NKCH) CP_WAIT1(); else CP_WAIT0();
        __syncthreads();

        const uint32_t st = sbase + s * STG_SZ;

        auto load_frag = [&](int kt, int buf) {
            const int acol = kt * 16 + acol_sub;
#pragma unroll
            for (int mt = 0; mt < 4; mt++) {
                int row = arow_base + mt * 16;
                LDSM4(ah[buf][mt][0], ah[buf][mt][1], ah[buf][mt][2], ah[buf][mt][3],
                      st + OFF_A + row * (PADK * 2) + acol * 2);
            }
            const int bcol = kt * 16 + bcol_sub;
#pragma unroll
            for (int pr = 0; pr < 4; pr++) {
                int row = wn * 64 + pr * 16 + brow_in;
                LDSM4(bf[buf][pr][0], bf[buf][pr][1], bf[buf][pr][2], bf[buf][pr][3],
                      st + OFF_B + row * (PADK * 2) + bcol * 2);
            }
        };

        load_frag(0, 0);
#pragma unroll
        for (int kt = 0; kt < 4; kt++) {
            const int cur = kt & 1;
            if (kt < 3) load_frag(kt + 1, cur ^ 1);
#pragma unroll
            for (int pr = 0; pr < 4; pr++) {
#pragma unroll
                for (int mt = 0; mt < 4; mt++) {
                    MMA16816(acc[mt][pr * 2],     ah[cur][mt], (&bf[cur][pr][0]));
                    MMA16816(acc[mt][pr * 2 + 1], ah[cur][mt], (&bf[cur][pr][2]));
                }
            }
        }

        if (t + 2 < NKCH) load_stage(t + 2, (t + 2) % NSTG);
    }

    // ---- epilogue: tanh(acc + ent) . v, quad-reduce, smem-combine, store ---
    const int quarter = blockIdx.x;
    const int halfA = quarter >> 1;
    float part[4][2];
#pragma unroll
    for (int mt = 0; mt < 4; mt++) {
#pragma unroll
        for (int h = 0; h < 2; h++) {
            const int l = l0 + wm * 64 + mt * 16 + (lane >> 2) + h * 8;
            const float e = g_dense_ent[b * A + 2 * l + halfA];
            float p = 0.f;
#pragma unroll
            for (int nt = 0; nt < 8; nt++) {
                int a = wn * 64 + nt * 8 + 2 * (lane & 3);
                p += sv[a]     * tanhf(acc[mt][nt][2 * h]     + e);
                p += sv[a + 1] * tanhf(acc[mt][nt][2 * h + 1] + e);
            }
            p += __shfl_xor_sync(0xffffffffu, p, 1);
            p += __shfl_xor_sync(0xffffffffu, p, 2);
            part[mt][h] = p;
            if (wn == 0 && (lane & 3) == 0)
                s_red[wm][mt][h][lane >> 2] = p;
        }
    }
    __syncthreads();
    if (wn == 1 && (lane & 3) == 0) {
#pragma unroll
        for (int mt = 0; mt < 4; mt++)
#pragma unroll
            for (int h = 0; h < 2; h++) {
                const int l = l0 + wm * 64 + mt * 16 + (lane >> 2) + h * 8;
                g_vu_part[quarter][b * L + l] =
                    part[mt][h] + s_red[wm][mt][h][lane >> 2];
            }
    }
}

// ---------------------------------------------------------------------------
// K4: softmax over L + partial z atomically into z (zeroed by k_prep).
// grid = (B, 8); 256 threads; 32 l-rows per CTA. (measured best config)
// ---------------------------------------------------------------------------
__global__ void __launch_bounds__(256)
k4_softmax_zp(float* __restrict__ z) {
    const int b = blockIdx.x;
    const int lq = blockIdx.y;
    const int tid = threadIdx.x;
    const int lane = tid & 31;
    const int wid = tid >> 5;

    __shared__ float sa[L];
    __shared__ float red[8];

    float vu = (g_vu_part[0][b * L + tid] + g_vu_part[1][b * L + tid])
             + (g_vu_part[2][b * L + tid] + g_vu_part[3][b * L + tid]);

    float m = vu;
#pragma unroll
    for (int off = 16; off; off >>= 1) m = fmaxf(m, __shfl_xor_sync(0xffffffffu, m, off));
    if (lane == 0) red[wid] = m;
    __syncthreads();
    if (tid < 8) {
        float mm = red[tid];
#pragma unroll
        for (int off = 4; off; off >>= 1) mm = fmaxf(mm, __shfl_xor_sync(0xffu, mm, off));
        if (tid == 0) red[0] = mm;
    }
    __syncthreads();
    const float mv = red[0];
    __syncthreads();

    float ex = expf(vu - mv);
    float ssum = ex;
#pragma unroll
    for (int off = 16; off; off >>= 1) ssum += __shfl_xor_sync(0xffffffffu, ssum, off);
    if (lane == 0) red[wid] = ssum;
    __syncthreads();
    if (tid < 8) {
        float ss = red[tid];
#pragma unroll
        for (int off = 4; off; off >>= 1) ss += __shfl_xor_sync(0xffu, ss, off);
        if (tid == 0) red[0] = ss;
    }
    __syncthreads();
    const float inv = 1.f / red[0];
    sa[tid] = ex * inv;
    __syncthreads();

    const int h4 = tid * 4;
    const __half* base = g_pf_h + ((size_t)b * L + lq * 32) * F + h4;
    float ax = 0.f, ay = 0.f, az = 0.f, aw = 0.f;
#pragma unroll
    for (int l2 = 0; l2 < 32; l2++) {
        uint2 raw = *(const uint2*)(base + (size_t)l2 * F);
        __half2 p0 = *(__half2*)&raw.x;
        __half2 p1 = *(__half2*)&raw.y;
        float2 f0 = __half22float2(p0);
        float2 f1 = __half22float2(p1);
        float s = sa[lq * 32 + l2];
        ax += s * f0.x; ay += s * f0.y; az += s * f1.x; aw += s * f1.y;
    }
    float* zb = z + (size_t)b * H + h4;
    atomicAdd(zb,     ax);
    atomicAdd(zb + 1, ay);
    atomicAdd(zb + 2, az);
    atomicAdd(zb + 3, aw);
}

// ---------------------------------------------------------------------------
extern "C" void kernel_launch(void* const* d_in, const int* in_sizes, int n_in,
                              void* d_out, int out_size) {
    const float* wh   = (const float*)d_in[0];
    const float* pe1  = (const float*)d_in[1];
    const float* pe2  = (const float*)d_in[2];
    const int*   e1e  = (const int*)d_in[3];
    const int*   e2e  = (const int*)d_in[4];
    const float* te   = (const float*)d_in[5];
    const float* Wp   = (const float*)d_in[6];
    const float* We   = (const float*)d_in[7];
    const float* v    = (const float*)d_in[8];
    float* z = (float*)d_out;

    cudaFuncSetAttribute(k3_main, cudaFuncAttributeMaxDynamicSharedMemorySize, K3_DSMEM);

    k_prep<<<NB_PF + NB_WP + NB_WE + NB_ENT, 256>>>(wh, pe1, pe2, Wp, We, e1e, e2e, te, z);
    k2_dense_ent<<<dim3(4, 32), 256>>>();
    k3_main<<<dim3(4, 128), 128, K3_DSMEM>>>(v);
    k4_softmax_zp<<<dim3(B, 8), 256>>>(z);
}